// round 8
// baseline (speedup 1.0000x reference)
#include <cuda_runtime.h>
#include <cstdint>

#define BATCH 8
#define C     192
#define CQ    32
#define NPIX  16384
#define SUB   64
#define NSUBT 4
#define TILE  (SUB*NSUBT)     // 256
#define NPARTS (NPIX/TILE)    // 64

typedef unsigned long long u64;

// ---------------- deterministic scratch ----------------
__device__ float g_part_kx  [BATCH*NPARTS*CQ*C];
__device__ float g_part_xsum[BATCH*NPARTS*C];
__device__ float g_part_ksum[BATCH*NPARTS*CQ];
__device__ float g_kx  [BATCH*CQ*C];
__device__ float g_xsum[BATCH*C];
__device__ float g_ksum[BATCH*CQ];
__device__ float g_mat [BATCH*CQ*C];
__device__ float g_vsum[BATCH*C];

// ---------------- packed f32x2 helpers ----------------
__device__ __forceinline__ u64 pack2dup(float x) {
    u64 r; asm("mov.b64 %0, {%1, %1};" : "=l"(r) : "f"(x)); return r;
}
__device__ __forceinline__ u64 pack2(float a, float b) {
    u64 r; asm("mov.b64 %0, {%1, %2};" : "=l"(r) : "f"(a), "f"(b)); return r;
}
__device__ __forceinline__ void unpack2(u64 v, float& lo, float& hi) {
    asm("mov.b64 {%0, %1}, %2;" : "=f"(lo), "=f"(hi) : "l"(v));
}
__device__ __forceinline__ u64 ffma2(u64 a, u64 b, u64 c) {
    u64 d; asm("fma.rn.f32x2 %0, %1, %2, %3;" : "=l"(d) : "l"(a), "l"(b), "l"(c));
    return d;
}
__device__ __forceinline__ u64 fmul2(u64 a, u64 b) {
    u64 d; asm("mul.rn.f32x2 %0, %1, %2;" : "=l"(d) : "l"(a), "l"(b)); return d;
}
__device__ __forceinline__ u64 fadd2(u64 a, u64 b) {
    u64 d; asm("add.rn.f32x2 %0, %1, %2;" : "=l"(d) : "l"(a), "l"(b)); return d;
}

// ---------------- smem layouts (float offsets) ----------------
// pass1: buf0 holds x1 [c][t] stride64 plain, then x stride64 SWIZZLED
#define P1_BUF0   0        // 12288
#define P1_WKD    12288    // dup weights [32][388] = 12416
#define P1_KN     24704    // [32][64] = 2048
#define P1_KSQ    26752    // [8][64]  = 512
#define P1_INVN   27264    // [64]
#define P1_WKP    27328    // [32]
#define P1_KSUML  27360    // [32]
#define P1_TOT    27392
#define SMEM1_BYTES (P1_TOT*4)

// pass2 (identical to R7/R5-measured layout)
#define P2_XS     0        // [192][64] = 12288
#define P2_WQ     12288    // [32][194] = 6208
#define P2_MATS   18496    // [32][192] = 6144
#define P2_QN     24640    // [32][64]  = 2048
#define P2_QSQ    26688    // [8][64]   = 512
#define P2_SDR    27200    // [8][64]   = 512
#define P2_INVN   27712    // [64]
#define P2_TS     27776    // [64]
#define P2_KSUM   27840    // [32]
#define P2_VSUM   27872    // [192]
#define P2_TOT    28064
#define SMEM2_BYTES (P2_TOT*4)

// swizzled x offset: element (c, t) at c*64 + (t ^ (2*(c&31)))
__device__ __forceinline__ int xoff(int c, int t) {
    return c * 64 + (t ^ (2 * (c & 31)));
}

// =============================================================================
// Pass 1: Kn, KX = Kn·x^T (t-pair accum, swizzled conflict-free), ksum, xsum
// =============================================================================
__global__ __launch_bounds__(256, 2)
void pass1_kernel(const float* __restrict__ x, const float* __restrict__ x1,
                  const float* __restrict__ Wk, const float* __restrict__ bk)
{
    extern __shared__ float sm[];
    float* buf0  = sm + P1_BUF0;
    float* wkd   = sm + P1_WKD;
    float* kn    = sm + P1_KN;
    float* ksq   = sm + P1_KSQ;
    float* invn  = sm + P1_INVN;
    float* wkp   = sm + P1_WKP;
    float* ksuml = sm + P1_KSUML;

    const int tid  = threadIdx.x;
    const int lane = tid & 31;
    const int wgrp = tid >> 5;
    const int b    = blockIdx.y;
    const int part = blockIdx.x;
    const int mg   = tid >> 4;       // proj, tid<128 -> 0..7
    const int pp   = tid & 15;
    const int qd   = 4 * pp;

    // stage Wk DUPLICATED: [m][2k]={w,w}, [m][2k+1]... stride 388
#pragma unroll
    for (int i = 0; i < 24; i++) {
        int idx = tid + 256 * i;
        int m = idx / 192, k = idx - m * 192;
        float v = Wk[idx];
        wkd[m * 388 + 2 * k]     = v;
        wkd[m * 388 + 2 * k + 1] = v;
    }
    if (tid < 32) ksuml[tid] = 0.f;

    float bkr[4];
    if (tid < 128) {
#pragma unroll
        for (int mi = 0; mi < 4; mi++) bkr[mi] = bk[mg * 4 + mi];
    }

    u64 macc[4][6];   // t-pair KX partials: m = wgrp*4+mi, d = lane+32e
#pragma unroll
    for (int mi = 0; mi < 4; mi++)
#pragma unroll
        for (int e = 0; e < 6; e++) macc[mi][e] = 0ull;
    u64 xacc = 0ull;  // t-pair xsum partial (tid<192, channel=tid)

    const float* x1b = x1 + (size_t)b * C * NPIX;
    const float* xb  = x  + (size_t)b * C * NPIX;

    for (int s = 0; s < NSUBT; s++) {
        const int n0 = part * TILE + s * SUB;
        __syncthreads();   // A: buf0/kn reuse guard

        // ---- stage x1 -> buf0[c][t] stride 64 PLAIN (float4) ----
#pragma unroll
        for (int i = 0; i < 12; i++) {
            int idx = tid + 256 * i;
            int c = idx >> 4, q = idx & 15;
            *(float4*)&buf0[c * 64 + 4 * q] =
                *(const float4*)&x1b[(size_t)c * NPIX + n0 + 4 * q];
        }
        __syncthreads();   // B

        u64 acc[4][2];
        float2 xr[24];
        if (tid < 128) {
            // ---- K projection: 4 m x 4 px, dup weights (no MOVs) ----
#pragma unroll
            for (int mi = 0; mi < 4; mi++) {
                u64 bb = pack2dup(bkr[mi]);
                acc[mi][0] = bb; acc[mi][1] = bb;
            }
#pragma unroll 6
            for (int k = 0; k < C; k += 2) {
                u64 xa0 = *(const u64*)&buf0[k * 64 + qd];
                u64 xa1 = *(const u64*)&buf0[k * 64 + qd + 2];
                u64 xc0 = *(const u64*)&buf0[(k + 1) * 64 + qd];
                u64 xc1 = *(const u64*)&buf0[(k + 1) * 64 + qd + 2];
#pragma unroll
                for (int mi = 0; mi < 4; mi++) {
                    const float* wp = &wkd[(mg * 4 + mi) * 388 + 2 * k];
                    u64 wld = *(const u64*)&wp[0];   // {w[k],w[k]}
                    u64 whd = *(const u64*)&wp[2];   // {w[k+1],w[k+1]}
                    acc[mi][0] = ffma2(xa0, wld, acc[mi][0]);
                    acc[mi][1] = ffma2(xa1, wld, acc[mi][1]);
                    acc[mi][0] = ffma2(xc0, whd, acc[mi][0]);
                    acc[mi][1] = ffma2(xc1, whd, acc[mi][1]);
                }
            }
            u64 sq0 = fmul2(acc[0][0], acc[0][0]);
            u64 sq1 = fmul2(acc[0][1], acc[0][1]);
#pragma unroll
            for (int mi = 1; mi < 4; mi++) {
                sq0 = ffma2(acc[mi][0], acc[mi][0], sq0);
                sq1 = ffma2(acc[mi][1], acc[mi][1], sq1);
            }
            *(u64*)&ksq[mg * 64 + qd]     = sq0;
            *(u64*)&ksq[mg * 64 + qd + 2] = sq1;
        } else {
            // ---- prefetch x channels 0..95 into regs ----
            const int u = tid - 128;
            const int plu = 2 * (u & 31);
#pragma unroll
            for (int i = 0; i < 24; i++) {
                int c = (u >> 5) + 4 * i;
                xr[i] = *(const float2*)&xb[(size_t)c * NPIX + n0 + plu];
            }
        }
        __syncthreads();   // C: proj reads done, ksq ready

        if (tid < 64) {
            float tot = 0.f;
#pragma unroll
            for (int g = 0; g < 8; g++) tot += ksq[g * 64 + tid];
            invn[tid] = rsqrtf(tot);
        }
        // ---- stage x SWIZZLED [c][t] (conflict-free writes) ----
        if (tid >= 128) {
            const int u = tid - 128;
            const int plu = 2 * (u & 31);
#pragma unroll
            for (int i = 0; i < 24; i++) {
                int c = (u >> 5) + 4 * i;
                *(float2*)&buf0[xoff(c, plu)] = xr[i];
            }
        } else {
            const int pl = 2 * lane;
#pragma unroll
            for (int i = 0; i < 24; i++) {
                int c = 96 + (tid >> 5) + 4 * i;
                *(float2*)&buf0[xoff(c, pl)] =
                    *(const float2*)&xb[(size_t)c * NPIX + n0 + pl];
            }
        }
        __syncthreads();   // D: invn + x ready

        if (tid < 128) {
            // ---- kn = K*inv (float4 store), ksum via 16-lane shfl ----
            float4 iv = *(const float4*)&invn[qd];
            u64 iv0 = pack2(iv.x, iv.y), iv1 = pack2(iv.z, iv.w);
            float ksump[4];
#pragma unroll
            for (int mi = 0; mi < 4; mi++) {
                u64 k0 = fmul2(acc[mi][0], iv0);
                u64 k1 = fmul2(acc[mi][1], iv1);
                float a0, a1, a2, a3;
                unpack2(k0, a0, a1); unpack2(k1, a2, a3);
                *(float4*)&kn[(mg * 4 + mi) * 64 + qd] =
                    make_float4(a0, a1, a2, a3);
                ksump[mi] = (a0 + a1) + (a2 + a3);
            }
#pragma unroll
            for (int off = 8; off; off >>= 1)
#pragma unroll
                for (int mi = 0; mi < 4; mi++)
                    ksump[mi] += __shfl_down_sync(0xffffffffu, ksump[mi], off, 16);
            if (pp == 0)
#pragma unroll
                for (int mi = 0; mi < 4; mi++) wkp[mg * 4 + mi] = ksump[mi];
        }
        __syncthreads();   // E: kn + wkp ready

        if (tid < 32) ksuml[tid] += wkp[tid];

        // ---- xsum partial (t-pairs, swizzled) ----
        if (tid < 192) {
            const int sx = 2 * (tid & 31);
#pragma unroll 8
            for (int t = 0; t < 32; t++)
                xacc = fadd2(xacc, *(const u64*)&buf0[tid * 64 + ((2 * t) ^ sx)]);
        }

        // ---- KX += kn·x^T (t-pair FFMA2, conflict-free swizzled xd) ----
        {
            const int sx = 2 * lane;
#pragma unroll 2
            for (int tp = 0; tp < 32; tp++) {
                u64 kd[4];
#pragma unroll
                for (int mi = 0; mi < 4; mi++)
                    kd[mi] = *(const u64*)&kn[(wgrp * 4 + mi) * 64 + 2 * tp];
                const int toff = (2 * tp) ^ sx;
                u64 xd[6];
#pragma unroll
                for (int e = 0; e < 6; e++)
                    xd[e] = *(const u64*)&buf0[(lane + 32 * e) * 64 + toff];
#pragma unroll
                for (int mi = 0; mi < 4; mi++)
#pragma unroll
                    for (int e = 0; e < 6; e++)
                        macc[mi][e] = ffma2(kd[mi], xd[e], macc[mi][e]);
            }
        }
    }

    __syncthreads();
    // ---- fold + write partials (coalesced STG.32) ----
    float* pm = g_part_kx + ((size_t)b * NPARTS + part) * CQ * C;
#pragma unroll
    for (int mi = 0; mi < 4; mi++)
#pragma unroll
        for (int e = 0; e < 6; e++) {
            float lo, hi; unpack2(macc[mi][e], lo, hi);
            pm[(wgrp * 4 + mi) * C + lane + 32 * e] = lo + hi;
        }
    if (tid < 192) {
        float lo, hi; unpack2(xacc, lo, hi);
        g_part_xsum[((size_t)b * NPARTS + part) * C + tid] = lo + hi;
    }
    if (tid < 32) g_part_ksum[((size_t)b * NPARTS + part) * CQ + tid] = ksuml[tid];
}

// =============================================================================
// mid1: reduce partials (fixed order, float4)
// =============================================================================
__global__ void mid1_kernel()
{
    const int MAT4 = BATCH * CQ * C / 4;
    const int XS4  = BATCH * C / 4;
    const int KS4  = BATCH * CQ / 4;
    int idx = blockIdx.x * blockDim.x + threadIdx.x;
    if (idx < MAT4) {
        int i4 = idx * 4;
        int bb = i4 / (CQ * C), r = i4 % (CQ * C);
        const float* p = g_part_kx + (size_t)bb * NPARTS * CQ * C + r;
        float4 a = make_float4(0.f, 0.f, 0.f, 0.f);
#pragma unroll 8
        for (int q = 0; q < NPARTS; q++) {
            float4 v = *(const float4*)&p[(size_t)q * CQ * C];
            a.x += v.x; a.y += v.y; a.z += v.z; a.w += v.w;
        }
        *(float4*)&g_kx[i4] = a;
    } else if (idx < MAT4 + XS4) {
        int i4 = (idx - MAT4) * 4;
        int bb = i4 / C, r = i4 % C;
        const float* p = g_part_xsum + (size_t)bb * NPARTS * C + r;
        float4 a = make_float4(0.f, 0.f, 0.f, 0.f);
#pragma unroll 8
        for (int q = 0; q < NPARTS; q++) {
            float4 v = *(const float4*)&p[q * C];
            a.x += v.x; a.y += v.y; a.z += v.z; a.w += v.w;
        }
        *(float4*)&g_xsum[i4] = a;
    } else if (idx < MAT4 + XS4 + KS4) {
        int i4 = (idx - MAT4 - XS4) * 4;
        int bb = i4 / CQ, r = i4 % CQ;
        const float* p = g_part_ksum + (size_t)bb * NPARTS * CQ + r;
        float4 a = make_float4(0.f, 0.f, 0.f, 0.f);
#pragma unroll 8
        for (int q = 0; q < NPARTS; q++) {
            float4 v = *(const float4*)&p[q * CQ];
            a.x += v.x; a.y += v.y; a.z += v.z; a.w += v.w;
        }
        *(float4*)&g_ksum[i4] = a;
    }
}

// =============================================================================
// mid2: matrix = KX·Wv^T + ksum·bv^T ; vsum = Wv·xsum + N·bv
// =============================================================================
__global__ __launch_bounds__(256)
void mid2_kernel(const float* __restrict__ Wv, const float* __restrict__ bv)
{
    __shared__ float kxs[32 * 193];
    __shared__ float wvs[24 * 193];
    __shared__ float xsum_s[192];
    __shared__ float ksum_s[32];
    const int tid = threadIdx.x;
    const int b = blockIdx.x >> 3;
    const int c0 = (blockIdx.x & 7) * 24;

#pragma unroll
    for (int i = 0; i < 24; i++) {
        int idx = tid + 256 * i;
        int m = idx / 192, d = idx - m * 192;
        kxs[m * 193 + d] = g_kx[b * (CQ * C) + idx];
    }
#pragma unroll
    for (int i = 0; i < 18; i++) {
        int idx = tid + 256 * i;
        int r = idx / 192, d = idx - r * 192;
        wvs[r * 193 + d] = Wv[(size_t)(c0 + r) * C + d];
    }
    if (tid < 192) xsum_s[tid] = g_xsum[b * C + tid];
    if (tid < 32)  ksum_s[tid] = g_ksum[b * CQ + tid];
    __syncthreads();

#pragma unroll
    for (int e = 0; e < 3; e++) {
        int o = tid + 256 * e;
        int m = o / 24, c = o - m * 24;
        float acc = ksum_s[m] * bv[c0 + c];
#pragma unroll 8
        for (int d = 0; d < 192; d++)
            acc = fmaf(kxs[m * 193 + d], wvs[c * 193 + d], acc);
        g_mat[b * (CQ * C) + m * C + c0 + c] = acc;
    }
    if (tid < 24) {
        float acc = (float)NPIX * bv[c0 + tid];
#pragma unroll 8
        for (int d = 0; d < 192; d++)
            acc = fmaf(wvs[tid * 193 + d], xsum_s[d], acc);
        g_vsum[b * C + c0 + tid] = acc;
    }
}

// =============================================================================
// Pass 2: Qn, fused tailor reduction, out = gamma*ts*(vsum + Qn·matrix)
// (unchanged from measured 111 µs version)
// =============================================================================
__global__ __launch_bounds__(256, 2)
void pass2_kernel(const float* __restrict__ x1,
                  const float* __restrict__ Wq, const float* __restrict__ bq,
                  const float* __restrict__ gamma, float* __restrict__ out)
{
    extern __shared__ float sm[];
    float* xs     = sm + P2_XS;
    float* wq     = sm + P2_WQ;
    float* mats   = sm + P2_MATS;
    float* qn     = sm + P2_QN;
    float* qsq    = sm + P2_QSQ;
    float* sdr    = sm + P2_SDR;
    float* invn   = sm + P2_INVN;
    float* ts_s   = sm + P2_TS;
    float* ksum_s = sm + P2_KSUM;
    float* vsum_s = sm + P2_VSUM;

    const int tid  = threadIdx.x;
    const int b    = blockIdx.y;
    const int part = blockIdx.x;
    const int mg   = tid >> 4;
    const int pp   = tid & 15;
    const int qd   = 4 * pp;
    const int cg   = tid >> 4;
    const float gm = gamma[0];

#pragma unroll
    for (int i = 0; i < 24; i++) {
        int idx = tid + 256 * i;
        int m = idx / 192, k = idx - m * 192;
        wq[m * 194 + k] = Wq[idx];
        mats[idx] = g_mat[(size_t)b * CQ * C + idx];
    }
    if (tid < 32)  ksum_s[tid] = g_ksum[b * CQ + tid] + 1e-6f;
    if (tid < 192) vsum_s[tid] = g_vsum[b * C + tid];

    float bqr[4];
    if (tid < 128) {
#pragma unroll
        for (int mi = 0; mi < 4; mi++) bqr[mi] = bq[mg * 4 + mi];
    }

    const float* x1b = x1 + (size_t)b * C * NPIX;
    float* outb = out + (size_t)b * C * NPIX;

    for (int s = 0; s < NSUBT; s++) {
        const int n0 = part * TILE + s * SUB;
        __syncthreads();   // A
        if (s == 0 || tid < 128) {
#pragma unroll
            for (int i = 0; i < 12; i++) {
                int idx = tid + 256 * i;
                int c = idx >> 4, q = idx & 15;
                *(float4*)&xs[c * 64 + 4 * q] =
                    *(const float4*)&x1b[(size_t)c * NPIX + n0 + 4 * q];
            }
        }
        __syncthreads();   // B

        u64 acc[4][2];
        float4 xr4[12];
        if (tid < 128) {
#pragma unroll
            for (int mi = 0; mi < 4; mi++) {
                u64 bb = pack2dup(bqr[mi]);
                acc[mi][0] = bb; acc[mi][1] = bb;
            }
#pragma unroll 6
            for (int k = 0; k < C; k += 2) {
                float4 xa = *(const float4*)&xs[k * 64 + qd];
                float4 xc = *(const float4*)&xs[(k + 1) * 64 + qd];
                u64 xa0 = pack2(xa.x, xa.y), xa1 = pack2(xa.z, xa.w);
                u64 xc0 = pack2(xc.x, xc.y), xc1 = pack2(xc.z, xc.w);
#pragma unroll
                for (int mi = 0; mi < 4; mi++) {
                    u64 w2 = *(const u64*)&wq[(mg * 4 + mi) * 194 + k];
                    float wl, wh; unpack2(w2, wl, wh);
                    u64 wld = pack2dup(wl), whd = pack2dup(wh);
                    acc[mi][0] = ffma2(xa0, wld, acc[mi][0]);
                    acc[mi][1] = ffma2(xa1, wld, acc[mi][1]);
                    acc[mi][0] = ffma2(xc0, whd, acc[mi][0]);
                    acc[mi][1] = ffma2(xc1, whd, acc[mi][1]);
                }
            }
            u64 sq0 = fmul2(acc[0][0], acc[0][0]);
            u64 sq1 = fmul2(acc[0][1], acc[0][1]);
            u64 sd0 = fmul2(acc[0][0], pack2dup(ksum_s[mg * 4]));
            u64 sd1 = fmul2(acc[0][1], pack2dup(ksum_s[mg * 4]));
#pragma unroll
            for (int mi = 1; mi < 4; mi++) {
                u64 ks = pack2dup(ksum_s[mg * 4 + mi]);
                sq0 = ffma2(acc[mi][0], acc[mi][0], sq0);
                sq1 = ffma2(acc[mi][1], acc[mi][1], sq1);
                sd0 = ffma2(acc[mi][0], ks, sd0);
                sd1 = ffma2(acc[mi][1], ks, sd1);
            }
            *(u64*)&qsq[mg * 64 + qd]     = sq0;
            *(u64*)&qsq[mg * 64 + qd + 2] = sq1;
            *(u64*)&sdr[mg * 64 + qd]     = sd0;
            *(u64*)&sdr[mg * 64 + qd + 2] = sd1;
        } else if (s < NSUBT - 1) {
            const int n1 = n0 + SUB;
#pragma unroll
            for (int i = 0; i < 12; i++) {
                int idx = tid + 256 * i;
                int c = idx >> 4, q = idx & 15;
                xr4[i] = *(const float4*)&x1b[(size_t)c * NPIX + n1 + 4 * q];
            }
        }
        __syncthreads();   // C

        if (tid < 64) {
            float tsq = 0.f, tsd = 0.f;
#pragma unroll
            for (int g = 0; g < 8; g++) {
                tsq += qsq[g * 64 + tid];
                tsd += sdr[g * 64 + tid];
            }
            float inv = rsqrtf(tsq);
            invn[tid] = inv;
            ts_s[tid] = 1.0f / ((float)NPIX + inv * tsd);
        }
        __syncthreads();   // D

        if (tid < 128) {
            float4 iv = *(const float4*)&invn[qd];
            u64 iv0 = pack2(iv.x, iv.y), iv1 = pack2(iv.z, iv.w);
#pragma unroll
            for (int mi = 0; mi < 4; mi++) {
                u64 q0 = fmul2(acc[mi][0], iv0);
                u64 q1 = fmul2(acc[mi][1], iv1);
                float a0, a1, a2, a3;
                unpack2(q0, a0, a1); unpack2(q1, a2, a3);
                *(float4*)&qn[(mg * 4 + mi) * 64 + qd] =
                    make_float4(a0, a1, a2, a3);
            }
        } else if (s < NSUBT - 1) {
#pragma unroll
            for (int i = 0; i < 12; i++) {
                int idx = tid + 256 * i;
                int c = idx >> 4, q = idx & 15;
                *(float4*)&xs[c * 64 + 4 * q] = xr4[i];
            }
        }
        __syncthreads();   // E

        u64 oacc[4][6];
#pragma unroll
        for (int e = 0; e < 6; e++) {
            u64 vp = *(const u64*)&vsum_s[cg * 12 + 2 * e];
            oacc[0][e] = vp; oacc[1][e] = vp; oacc[2][e] = vp; oacc[3][e] = vp;
        }
#pragma unroll 4
        for (int m = 0; m < CQ; m++) {
            float4 qv = *(const float4*)&qn[m * 64 + qd];
            u64 q0 = pack2dup(qv.x), q1 = pack2dup(qv.y);
            u64 q2 = pack2dup(qv.z), q3 = pack2dup(qv.w);
#pragma unroll
            for (int e = 0; e < 6; e++) {
                u64 w2 = *(const u64*)&mats[m * 192 + cg * 12 + 2 * e];
                oacc[0][e] = ffma2(w2, q0, oacc[0][e]);
                oacc[1][e] = ffma2(w2, q1, oacc[1][e]);
                oacc[2][e] = ffma2(w2, q2, oacc[2][e]);
                oacc[3][e] = ffma2(w2, q3, oacc[3][e]);
            }
        }
        {
            float4 tv = *(const float4*)&ts_s[qd];
            u64 g0 = pack2dup(gm * tv.x), g1 = pack2dup(gm * tv.y);
            u64 g2 = pack2dup(gm * tv.z), g3 = pack2dup(gm * tv.w);
#pragma unroll
            for (int e = 0; e < 6; e++) {
                u64 o0 = fmul2(oacc[0][e], g0);
                u64 o1 = fmul2(oacc[1][e], g1);
                u64 o2 = fmul2(oacc[2][e], g2);
                u64 o3 = fmul2(oacc[3][e], g3);
                float l0, h0, l1, h1, l2, h2, l3, h3;
                unpack2(o0, l0, h0); unpack2(o1, l1, h1);
                unpack2(o2, l2, h2); unpack2(o3, l3, h3);
                const int c = cg * 12 + 2 * e;
                *(float4*)&outb[(size_t)c * NPIX + n0 + qd] =
                    make_float4(l0, l1, l2, l3);
                *(float4*)&outb[(size_t)(c + 1) * NPIX + n0 + qd] =
                    make_float4(h0, h1, h2, h3);
            }
        }
    }
}

// =============================================================================
extern "C" void kernel_launch(void* const* d_in, const int* in_sizes, int n_in,
                              void* d_out, int out_size)
{
    const float* x     = (const float*)d_in[0];
    const float* x1    = (const float*)d_in[1];
    const float* Wq    = (const float*)d_in[2];
    const float* bq    = (const float*)d_in[3];
    const float* Wk    = (const float*)d_in[4];
    const float* bk    = (const float*)d_in[5];
    const float* Wv    = (const float*)d_in[6];
    const float* bv    = (const float*)d_in[7];
    const float* gamma = (const float*)d_in[8];
    float* out = (float*)d_out;

    cudaFuncSetAttribute(pass1_kernel,
                         cudaFuncAttributeMaxDynamicSharedMemorySize, SMEM1_BYTES);
    cudaFuncSetAttribute(pass2_kernel,
                         cudaFuncAttributeMaxDynamicSharedMemorySize, SMEM2_BYTES);

    dim3 grid(NPARTS, BATCH);
    pass1_kernel<<<grid, 256, SMEM1_BYTES>>>(x, x1, Wk, bk);

    const int R4 = BATCH * CQ * C / 4 + BATCH * C / 4 + BATCH * CQ / 4;
    mid1_kernel<<<(R4 + 255) / 256, 256>>>();
    mid2_kernel<<<64, 256>>>(Wv, bv);

    pass2_kernel<<<grid, 256, SMEM2_BYTES>>>(x1, Wq, bq, gamma, out);
}

// round 9
// speedup vs baseline: 1.2018x; 1.2018x over previous
#include <cuda_runtime.h>
#include <cstdint>

#define BATCH 8
#define C     192
#define CQ    32
#define NPIX  16384
#define SUB   64
#define NSUBT 4
#define TILE  (SUB*NSUBT)     // 256
#define NPARTS (NPIX/TILE)    // 64

typedef unsigned long long u64;

// ---------------- deterministic scratch ----------------
__device__ float g_part_kx  [BATCH*NPARTS*CQ*C];
__device__ float g_part_xsum[BATCH*NPARTS*C];
__device__ float g_part_ksum[BATCH*NPARTS*CQ];
__device__ float g_kx  [BATCH*CQ*C];
__device__ float g_xsum[BATCH*C];
__device__ float g_ksum[BATCH*CQ];
__device__ float g_mat [BATCH*CQ*C];
__device__ float g_vsum[BATCH*C];

// ---------------- packed f32x2 helpers ----------------
__device__ __forceinline__ u64 pack2dup(float x) {
    u64 r; asm("mov.b64 %0, {%1, %1};" : "=l"(r) : "f"(x)); return r;
}
__device__ __forceinline__ u64 pack2(float a, float b) {
    u64 r; asm("mov.b64 %0, {%1, %2};" : "=l"(r) : "f"(a), "f"(b)); return r;
}
__device__ __forceinline__ void unpack2(u64 v, float& lo, float& hi) {
    asm("mov.b64 {%0, %1}, %2;" : "=f"(lo), "=f"(hi) : "l"(v));
}
__device__ __forceinline__ u64 ffma2(u64 a, u64 b, u64 c) {
    u64 d; asm("fma.rn.f32x2 %0, %1, %2, %3;" : "=l"(d) : "l"(a), "l"(b), "l"(c));
    return d;
}
__device__ __forceinline__ u64 fmul2(u64 a, u64 b) {
    u64 d; asm("mul.rn.f32x2 %0, %1, %2;" : "=l"(d) : "l"(a), "l"(b)); return d;
}
__device__ __forceinline__ u64 fadd2(u64 a, u64 b) {
    u64 d; asm("add.rn.f32x2 %0, %1, %2;" : "=l"(d) : "l"(a), "l"(b)); return d;
}

// ---------------- smem layouts (float offsets) ----------------
// pass1: buf0 = x1 [192][64] (stride 64) then xt [64][194]
#define P1_BUF0   0        // 12416
#define P1_WK     12416    // [32][196] = 6272
#define P1_KN     18688    // [32][64]  = 2048
#define P1_KSQ    20736    // [8][64]   = 512
#define P1_INVN   21248    // [64]
#define P1_WKP    21312    // [32]
#define P1_KSUML  21344    // [32]
#define P1_TOT    21376
#define SMEM1_BYTES (P1_TOT*4)

// pass2
#define P2_XS     0        // [192][64] = 12288
#define P2_WQ     12288    // [32][196] = 6272
#define P2_MATS   18560    // [32][192] = 6144
#define P2_QN     24704    // [32][64]  = 2048
#define P2_QSQ    26752    // [8][64]   = 512
#define P2_SDP    27264    // [8][64]   = 512
#define P2_INVN   27776    // [64]
#define P2_TS     27840    // [64]
#define P2_KSUM   27904    // [32]
#define P2_VSUM   27936    // [192]
#define P2_TOT    28128
#define SMEM2_BYTES (P2_TOT*4)

// =============================================================================
// Pass 1: Kn, KX = Kn·x^T, ksum, xsum (per-block partials)  [R5 structure]
//   proj (tid<128): mg=tid>>4 (m=mg*4+mi), qd=4*(tid&15)
//   KX: m = wgrp+8i, d-pair = pl+64j
// =============================================================================
__global__ __launch_bounds__(256, 2)
void pass1_kernel(const float* __restrict__ x, const float* __restrict__ x1,
                  const float* __restrict__ Wk, const float* __restrict__ bk)
{
    extern __shared__ float sm[];
    float* buf0  = sm + P1_BUF0;
    float* wk    = sm + P1_WK;
    float* kn    = sm + P1_KN;
    float* ksq   = sm + P1_KSQ;
    float* invn  = sm + P1_INVN;
    float* wkp   = sm + P1_WKP;
    float* ksuml = sm + P1_KSUML;

    const int tid  = threadIdx.x;
    const int lane = tid & 31;
    const int wgrp = tid >> 5;
    const int b    = blockIdx.y;
    const int part = blockIdx.x;
    const int pl   = 2 * lane;
    const int mg   = tid >> 4;       // proj, tid<128 -> 0..7
    const int pp   = tid & 15;
    const int qd   = 4 * pp;

    // stage Wk [m][k] stride 196 (16B-aligned rows)
#pragma unroll
    for (int i = 0; i < 24; i++) {
        int idx = tid + 256 * i;
        int m = idx / 192, k = idx - m * 192;
        wk[m * 196 + k] = Wk[idx];
    }
    if (tid < 32) ksuml[tid] = 0.f;

    float bkr[4];
    if (tid < 128) {
#pragma unroll
        for (int mi = 0; mi < 4; mi++) bkr[mi] = bk[mg * 4 + mi];
    }

    u64 macc[4][3];   // KX: m = wgrp+8i, d-pair = pl + 64j
#pragma unroll
    for (int i = 0; i < 4; i++)
#pragma unroll
        for (int j = 0; j < 3; j++) macc[i][j] = 0ull;
    u64 xacc = 0ull;  // xsum partial (tid<96, ch pair 2*tid)

    const float* x1b = x1 + (size_t)b * C * NPIX;
    const float* xb  = x  + (size_t)b * C * NPIX;

    for (int s = 0; s < NSUBT; s++) {
        const int n0 = part * TILE + s * SUB;
        __syncthreads();   // A: buf0/kn reuse guard

        // ---- stage x1 -> buf0[c][t] stride 64 (float4) ----
#pragma unroll
        for (int i = 0; i < 12; i++) {
            int idx = tid + 256 * i;
            int c = idx >> 4, q = idx & 15;
            *(float4*)&buf0[c * 64 + 4 * q] =
                *(const float4*)&x1b[(size_t)c * NPIX + n0 + 4 * q];
        }
        __syncthreads();   // B

        u64 acc[4][2];
        float2 xr[24];
        if (tid < 128) {
            // ---- K projection: 4 m x 4 px, LDS.128 weights ----
#pragma unroll
            for (int mi = 0; mi < 4; mi++) {
                u64 bb = pack2dup(bkr[mi]);
                acc[mi][0] = bb; acc[mi][1] = bb;
            }
#pragma unroll 3
            for (int k = 0; k < C; k += 4) {
                float4 xa = *(const float4*)&buf0[k * 64 + qd];
                float4 xc = *(const float4*)&buf0[(k + 1) * 64 + qd];
                float4 xe = *(const float4*)&buf0[(k + 2) * 64 + qd];
                float4 xg = *(const float4*)&buf0[(k + 3) * 64 + qd];
                u64 xa0 = pack2(xa.x, xa.y), xa1 = pack2(xa.z, xa.w);
                u64 xc0 = pack2(xc.x, xc.y), xc1 = pack2(xc.z, xc.w);
                u64 xe0 = pack2(xe.x, xe.y), xe1 = pack2(xe.z, xe.w);
                u64 xg0 = pack2(xg.x, xg.y), xg1 = pack2(xg.z, xg.w);
#pragma unroll
                for (int mi = 0; mi < 4; mi++) {
                    float4 w = *(const float4*)&wk[(mg * 4 + mi) * 196 + k];
                    u64 w0 = pack2dup(w.x), w1 = pack2dup(w.y);
                    u64 w2 = pack2dup(w.z), w3 = pack2dup(w.w);
                    acc[mi][0] = ffma2(xa0, w0, acc[mi][0]);
                    acc[mi][1] = ffma2(xa1, w0, acc[mi][1]);
                    acc[mi][0] = ffma2(xc0, w1, acc[mi][0]);
                    acc[mi][1] = ffma2(xc1, w1, acc[mi][1]);
                    acc[mi][0] = ffma2(xe0, w2, acc[mi][0]);
                    acc[mi][1] = ffma2(xe1, w2, acc[mi][1]);
                    acc[mi][0] = ffma2(xg0, w3, acc[mi][0]);
                    acc[mi][1] = ffma2(xg1, w3, acc[mi][1]);
                }
            }
            u64 sq0 = fmul2(acc[0][0], acc[0][0]);
            u64 sq1 = fmul2(acc[0][1], acc[0][1]);
#pragma unroll
            for (int mi = 1; mi < 4; mi++) {
                sq0 = ffma2(acc[mi][0], acc[mi][0], sq0);
                sq1 = ffma2(acc[mi][1], acc[mi][1], sq1);
            }
            *(u64*)&ksq[mg * 64 + qd]     = sq0;
            *(u64*)&ksq[mg * 64 + qd + 2] = sq1;
        } else {
            // ---- prefetch x channels 0..95 into regs ----
            const int u = tid - 128;
            const int plu = 2 * (u & 31);
#pragma unroll
            for (int i = 0; i < 24; i++) {
                int c = (u >> 5) + 4 * i;
                xr[i] = *(const float2*)&xb[(size_t)c * NPIX + n0 + plu];
            }
        }
        __syncthreads();   // C: proj reads done, ksq ready

        if (tid < 64) {
            float tot = 0.f;
#pragma unroll
            for (int g = 0; g < 8; g++) tot += ksq[g * 64 + tid];
            invn[tid] = rsqrtf(tot);
        }
        if (tid >= 128) {
            // store prefetched x transposed -> buf0 = xt[t][194]
            const int u = tid - 128;
            const int plu = 2 * (u & 31);
#pragma unroll
            for (int i = 0; i < 24; i++) {
                int c = (u >> 5) + 4 * i;
                buf0[plu * 194 + c]       = xr[i].x;
                buf0[(plu + 1) * 194 + c] = xr[i].y;
            }
        } else {
            // load+store x channels 96..191 transposed
#pragma unroll
            for (int i = 0; i < 24; i++) {
                int c = 96 + (tid >> 5) + 4 * i;
                float2 v = *(const float2*)&xb[(size_t)c * NPIX + n0 + pl];
                buf0[pl * 194 + c]       = v.x;
                buf0[(pl + 1) * 194 + c] = v.y;
            }
        }
        __syncthreads();   // D: invn + xt ready

        if (tid < 128) {
            // ---- kn = K*inv (float4 store), ksum via 16-lane shfl ----
            float4 iv = *(const float4*)&invn[qd];
            u64 iv0 = pack2(iv.x, iv.y), iv1 = pack2(iv.z, iv.w);
            float ksump[4];
#pragma unroll
            for (int mi = 0; mi < 4; mi++) {
                u64 k0 = fmul2(acc[mi][0], iv0);
                u64 k1 = fmul2(acc[mi][1], iv1);
                float a0, a1, a2, a3;
                unpack2(k0, a0, a1); unpack2(k1, a2, a3);
                *(float4*)&kn[(mg * 4 + mi) * 64 + qd] =
                    make_float4(a0, a1, a2, a3);
                ksump[mi] = (a0 + a1) + (a2 + a3);
            }
#pragma unroll
            for (int off = 8; off; off >>= 1)
#pragma unroll
                for (int mi = 0; mi < 4; mi++)
                    ksump[mi] += __shfl_down_sync(0xffffffffu, ksump[mi], off, 16);
            if (pp == 0)
#pragma unroll
                for (int mi = 0; mi < 4; mi++) wkp[mg * 4 + mi] = ksump[mi];
        }
        __syncthreads();   // E: kn + wkp ready

        if (tid < 32) ksuml[tid] += wkp[tid];

        // ---- xsum partial (pairs from xt rows) ----
        if (tid < 96) {
            u64 sv = 0ull;
#pragma unroll 8
            for (int t = 0; t < SUB; t++)
                sv = fadd2(sv, *(const u64*)&buf0[t * 194 + 2 * tid]);
            xacc = fadd2(xacc, sv);
        }

        // ---- KX += kn·x^T (t-block-4, broadcast kn LDS.128) ----
#pragma unroll 4
        for (int tb = 0; tb < 16; tb++) {
            const int t0 = 4 * tb;
            float4 kd[4];
#pragma unroll
            for (int i = 0; i < 4; i++)
                kd[i] = *(const float4*)&kn[(wgrp + 8 * i) * 64 + t0];
#pragma unroll
            for (int tt = 0; tt < 4; tt++) {
                u64 x2[3];
#pragma unroll
                for (int j = 0; j < 3; j++)
                    x2[j] = *(const u64*)&buf0[(t0 + tt) * 194 + pl + 64 * j];
                const float* kf0 = (const float*)&kd[0];
                const float* kf1 = (const float*)&kd[1];
                const float* kf2 = (const float*)&kd[2];
                const float* kf3 = (const float*)&kd[3];
                u64 kd0 = pack2dup(kf0[tt]);
                u64 kd1 = pack2dup(kf1[tt]);
                u64 kd2 = pack2dup(kf2[tt]);
                u64 kd3 = pack2dup(kf3[tt]);
#pragma unroll
                for (int j = 0; j < 3; j++) {
                    macc[0][j] = ffma2(kd0, x2[j], macc[0][j]);
                    macc[1][j] = ffma2(kd1, x2[j], macc[1][j]);
                    macc[2][j] = ffma2(kd2, x2[j], macc[2][j]);
                    macc[3][j] = ffma2(kd3, x2[j], macc[3][j]);
                }
            }
        }
    }

    __syncthreads();
    float* pm = g_part_kx + ((size_t)b * NPARTS + part) * CQ * C;
#pragma unroll
    for (int i = 0; i < 4; i++)
#pragma unroll
        for (int j = 0; j < 3; j++)
            *(u64*)&pm[(wgrp + 8 * i) * C + pl + 64 * j] = macc[i][j];
    if (tid < 96) {
        float lo, hi; unpack2(xacc, lo, hi);
        float* px = g_part_xsum + ((size_t)b * NPARTS + part) * C;
        px[2 * tid] = lo; px[2 * tid + 1] = hi;
    }
    if (tid < 32) g_part_ksum[((size_t)b * NPARTS + part) * CQ + tid] = ksuml[tid];
}

// =============================================================================
// mid1: reduce partials (fixed order, float4)
// =============================================================================
__global__ void mid1_kernel()
{
    const int MAT4 = BATCH * CQ * C / 4;
    const int XS4  = BATCH * C / 4;
    const int KS4  = BATCH * CQ / 4;
    int idx = blockIdx.x * blockDim.x + threadIdx.x;
    if (idx < MAT4) {
        int i4 = idx * 4;
        int bb = i4 / (CQ * C), r = i4 % (CQ * C);
        const float* p = g_part_kx + (size_t)bb * NPARTS * CQ * C + r;
        float4 a = make_float4(0.f, 0.f, 0.f, 0.f);
#pragma unroll 8
        for (int q = 0; q < NPARTS; q++) {
            float4 v = *(const float4*)&p[(size_t)q * CQ * C];
            a.x += v.x; a.y += v.y; a.z += v.z; a.w += v.w;
        }
        *(float4*)&g_kx[i4] = a;
    } else if (idx < MAT4 + XS4) {
        int i4 = (idx - MAT4) * 4;
        int bb = i4 / C, r = i4 % C;
        const float* p = g_part_xsum + (size_t)bb * NPARTS * C + r;
        float4 a = make_float4(0.f, 0.f, 0.f, 0.f);
#pragma unroll 8
        for (int q = 0; q < NPARTS; q++) {
            float4 v = *(const float4*)&p[q * C];
            a.x += v.x; a.y += v.y; a.z += v.z; a.w += v.w;
        }
        *(float4*)&g_xsum[i4] = a;
    } else if (idx < MAT4 + XS4 + KS4) {
        int i4 = (idx - MAT4 - XS4) * 4;
        int bb = i4 / CQ, r = i4 % CQ;
        const float* p = g_part_ksum + (size_t)bb * NPARTS * CQ + r;
        float4 a = make_float4(0.f, 0.f, 0.f, 0.f);
#pragma unroll 8
        for (int q = 0; q < NPARTS; q++) {
            float4 v = *(const float4*)&p[q * CQ];
            a.x += v.x; a.y += v.y; a.z += v.z; a.w += v.w;
        }
        *(float4*)&g_ksum[i4] = a;
    }
}

// =============================================================================
// mid2: matrix = KX·Wv^T + ksum·bv^T ; vsum = Wv·xsum + N·bv
// =============================================================================
__global__ __launch_bounds__(256)
void mid2_kernel(const float* __restrict__ Wv, const float* __restrict__ bv)
{
    __shared__ float kxs[32 * 193];
    __shared__ float wvs[24 * 193];
    __shared__ float xsum_s[192];
    __shared__ float ksum_s[32];
    const int tid = threadIdx.x;
    const int b = blockIdx.x >> 3;
    const int c0 = (blockIdx.x & 7) * 24;

#pragma unroll
    for (int i = 0; i < 24; i++) {
        int idx = tid + 256 * i;
        int m = idx / 192, d = idx - m * 192;
        kxs[m * 193 + d] = g_kx[b * (CQ * C) + idx];
    }
#pragma unroll
    for (int i = 0; i < 18; i++) {
        int idx = tid + 256 * i;
        int r = idx / 192, d = idx - r * 192;
        wvs[r * 193 + d] = Wv[(size_t)(c0 + r) * C + d];
    }
    if (tid < 192) xsum_s[tid] = g_xsum[b * C + tid];
    if (tid < 32)  ksum_s[tid] = g_ksum[b * CQ + tid];
    __syncthreads();

#pragma unroll
    for (int e = 0; e < 3; e++) {
        int o = tid + 256 * e;
        int m = o / 24, c = o - m * 24;
        float acc = ksum_s[m] * bv[c0 + c];
#pragma unroll 8
        for (int d = 0; d < 192; d++)
            acc = fmaf(kxs[m * 193 + d], wvs[c * 193 + d], acc);
        g_mat[b * (CQ * C) + m * C + c0 + c] = acc;
    }
    if (tid < 24) {
        float acc = (float)NPIX * bv[c0 + tid];
#pragma unroll 8
        for (int d = 0; d < 192; d++)
            acc = fmaf(wvs[tid * 193 + d], xsum_s[d], acc);
        g_vsum[b * C + c0 + tid] = acc;
    }
}

// =============================================================================
// Pass 2: Qn, tailor_sum, out = gamma*ts*(vsum + Qn·matrix)  [R5 structure]
// =============================================================================
__global__ __launch_bounds__(256, 2)
void pass2_kernel(const float* __restrict__ x1,
                  const float* __restrict__ Wq, const float* __restrict__ bq,
                  const float* __restrict__ gamma, float* __restrict__ out)
{
    extern __shared__ float sm[];
    float* xs     = sm + P2_XS;
    float* wq     = sm + P2_WQ;
    float* mats   = sm + P2_MATS;
    float* qn     = sm + P2_QN;
    float* qsq    = sm + P2_QSQ;
    float* sdp    = sm + P2_SDP;
    float* invn   = sm + P2_INVN;
    float* ts_s   = sm + P2_TS;
    float* ksum_s = sm + P2_KSUM;
    float* vsum_s = sm + P2_VSUM;

    const int tid  = threadIdx.x;
    const int b    = blockIdx.y;
    const int part = blockIdx.x;
    const int mg   = tid >> 4;      // proj (tid<128)
    const int pp   = tid & 15;
    const int qd   = 4 * pp;
    const int cg   = tid >> 4;      // out-GEMM ch-group
    const float gm = gamma[0];

#pragma unroll
    for (int i = 0; i < 24; i++) {
        int idx = tid + 256 * i;
        int m = idx / 192, k = idx - m * 192;
        wq[m * 196 + k] = Wq[idx];
        mats[idx] = g_mat[(size_t)b * CQ * C + idx];
    }
    if (tid < 32)  ksum_s[tid] = g_ksum[b * CQ + tid] + 1e-6f;
    if (tid < 192) vsum_s[tid] = g_vsum[b * C + tid];

    float bqr[4];
    if (tid < 128) {
#pragma unroll
        for (int mi = 0; mi < 4; mi++) bqr[mi] = bq[mg * 4 + mi];
    }

    const float* x1b = x1 + (size_t)b * C * NPIX;
    float* outb = out + (size_t)b * C * NPIX;

    for (int s = 0; s < NSUBT; s++) {
        const int n0 = part * TILE + s * SUB;
        __syncthreads();   // A
        if (s == 0 || tid < 128) {
#pragma unroll
            for (int i = 0; i < 12; i++) {
                int idx = tid + 256 * i;
                int c = idx >> 4, q = idx & 15;
                *(float4*)&xs[c * 64 + 4 * q] =
                    *(const float4*)&x1b[(size_t)c * NPIX + n0 + 4 * q];
            }
        }
        __syncthreads();   // B

        u64 acc[4][2];
        float4 xr4[12];
        if (tid < 128) {
            // ---- Q projection: LDS.128 weights ----
#pragma unroll
            for (int mi = 0; mi < 4; mi++) {
                u64 bb = pack2dup(bqr[mi]);
                acc[mi][0] = bb; acc[mi][1] = bb;
            }
#pragma unroll 3
            for (int k = 0; k < C; k += 4) {
                float4 xa = *(const float4*)&xs[k * 64 + qd];
                float4 xc = *(const float4*)&xs[(k + 1) * 64 + qd];
                float4 xe = *(const float4*)&xs[(k + 2) * 64 + qd];
                float4 xg = *(const float4*)&xs[(k + 3) * 64 + qd];
                u64 xa0 = pack2(xa.x, xa.y), xa1 = pack2(xa.z, xa.w);
                u64 xc0 = pack2(xc.x, xc.y), xc1 = pack2(xc.z, xc.w);
                u64 xe0 = pack2(xe.x, xe.y), xe1 = pack2(xe.z, xe.w);
                u64 xg0 = pack2(xg.x, xg.y), xg1 = pack2(xg.z, xg.w);
#pragma unroll
                for (int mi = 0; mi < 4; mi++) {
                    float4 w = *(const float4*)&wq[(mg * 4 + mi) * 196 + k];
                    u64 w0 = pack2dup(w.x), w1 = pack2dup(w.y);
                    u64 w2 = pack2dup(w.z), w3 = pack2dup(w.w);
                    acc[mi][0] = ffma2(xa0, w0, acc[mi][0]);
                    acc[mi][1] = ffma2(xa1, w0, acc[mi][1]);
                    acc[mi][0] = ffma2(xc0, w1, acc[mi][0]);
                    acc[mi][1] = ffma2(xc1, w1, acc[mi][1]);
                    acc[mi][0] = ffma2(xe0, w2, acc[mi][0]);
                    acc[mi][1] = ffma2(xe1, w2, acc[mi][1]);
                    acc[mi][0] = ffma2(xg0, w3, acc[mi][0]);
                    acc[mi][1] = ffma2(xg1, w3, acc[mi][1]);
                }
            }
            u64 sq0 = fmul2(acc[0][0], acc[0][0]);
            u64 sq1 = fmul2(acc[0][1], acc[0][1]);
#pragma unroll
            for (int mi = 1; mi < 4; mi++) {
                sq0 = ffma2(acc[mi][0], acc[mi][0], sq0);
                sq1 = ffma2(acc[mi][1], acc[mi][1], sq1);
            }
            *(u64*)&qsq[mg * 64 + qd]     = sq0;
            *(u64*)&qsq[mg * 64 + qd + 2] = sq1;
        } else if (s < NSUBT - 1) {
            // ---- prefetch next subtile (upper half of staging pattern) ----
            const int n1 = n0 + SUB;
#pragma unroll
            for (int i = 0; i < 12; i++) {
                int idx = tid + 256 * i;
                int c = idx >> 4, q = idx & 15;
                xr4[i] = *(const float4*)&x1b[(size_t)c * NPIX + n1 + 4 * q];
            }
        }
        __syncthreads();   // C

        if (tid < 64) {
            float tot = 0.f;
#pragma unroll
            for (int g = 0; g < 8; g++) tot += qsq[g * 64 + tid];
            invn[tid] = rsqrtf(tot);
        }
        __syncthreads();   // D

        if (tid < 128) {
            float4 iv = *(const float4*)&invn[qd];
            u64 iv0 = pack2(iv.x, iv.y), iv1 = pack2(iv.z, iv.w);
            u64 sd0 = 0ull, sd1 = 0ull;
#pragma unroll
            for (int mi = 0; mi < 4; mi++) {
                u64 q0 = fmul2(acc[mi][0], iv0);
                u64 q1 = fmul2(acc[mi][1], iv1);
                float a0, a1, a2, a3;
                unpack2(q0, a0, a1); unpack2(q1, a2, a3);
                *(float4*)&qn[(mg * 4 + mi) * 64 + qd] =
                    make_float4(a0, a1, a2, a3);
                u64 ks = pack2dup(ksum_s[mg * 4 + mi]);
                sd0 = ffma2(q0, ks, sd0);
                sd1 = ffma2(q1, ks, sd1);
            }
            *(u64*)&sdp[mg * 64 + qd]     = sd0;
            *(u64*)&sdp[mg * 64 + qd + 2] = sd1;
        }
        __syncthreads();   // E

        if (tid < 64) {
            float tot = 0.f;
#pragma unroll
            for (int g = 0; g < 8; g++) tot += sdp[g * 64 + tid];
            ts_s[tid] = 1.0f / ((float)NPIX + tot);
        }
        __syncthreads();   // F

        if (tid >= 128 && s < NSUBT - 1) {
#pragma unroll
            for (int i = 0; i < 12; i++) {
                int idx = tid + 256 * i;
                int c = idx >> 4, q = idx & 15;
                *(float4*)&xs[c * 64 + 4 * q] = xr4[i];
            }
        }

        // ---- out GEMM: 4 px x 12 ch per thread ----
        u64 oacc[4][6];
#pragma unroll
        for (int e = 0; e < 6; e++) {
            u64 vp = *(const u64*)&vsum_s[cg * 12 + 2 * e];
            oacc[0][e] = vp; oacc[1][e] = vp; oacc[2][e] = vp; oacc[3][e] = vp;
        }
#pragma unroll 4
        for (int m = 0; m < CQ; m++) {
            float4 qv = *(const float4*)&qn[m * 64 + qd];
            u64 q0 = pack2dup(qv.x), q1 = pack2dup(qv.y);
            u64 q2 = pack2dup(qv.z), q3 = pack2dup(qv.w);
#pragma unroll
            for (int e = 0; e < 6; e++) {
                u64 w2 = *(const u64*)&mats[m * 192 + cg * 12 + 2 * e];
                oacc[0][e] = ffma2(w2, q0, oacc[0][e]);
                oacc[1][e] = ffma2(w2, q1, oacc[1][e]);
                oacc[2][e] = ffma2(w2, q2, oacc[2][e]);
                oacc[3][e] = ffma2(w2, q3, oacc[3][e]);
            }
        }
        {
            float4 tv = *(const float4*)&ts_s[qd];
            u64 g0 = pack2dup(gm * tv.x), g1 = pack2dup(gm * tv.y);
            u64 g2 = pack2dup(gm * tv.z), g3 = pack2dup(gm * tv.w);
#pragma unroll
            for (int e = 0; e < 6; e++) {
                u64 o0 = fmul2(oacc[0][e], g0);
                u64 o1 = fmul2(oacc[1][e], g1);
                u64 o2 = fmul2(oacc[2][e], g2);
                u64 o3 = fmul2(oacc[3][e], g3);
                float l0, h0, l1, h1, l2, h2, l3, h3;
                unpack2(o0, l0, h0); unpack2(o1, l1, h1);
                unpack2(o2, l2, h2); unpack2(o3, l3, h3);
                const int c = cg * 12 + 2 * e;
                *(float4*)&outb[(size_t)c * NPIX + n0 + qd] =
                    make_float4(l0, l1, l2, l3);
                *(float4*)&outb[(size_t)(c + 1) * NPIX + n0 + qd] =
                    make_float4(h0, h1, h2, h3);
            }
        }
    }
}

// =============================================================================
extern "C" void kernel_launch(void* const* d_in, const int* in_sizes, int n_in,
                              void* d_out, int out_size)
{
    const float* x     = (const float*)d_in[0];
    const float* x1    = (const float*)d_in[1];
    const float* Wq    = (const float*)d_in[2];
    const float* bq    = (const float*)d_in[3];
    const float* Wk    = (const float*)d_in[4];
    const float* bk    = (const float*)d_in[5];
    const float* Wv    = (const float*)d_in[6];
    const float* bv    = (const float*)d_in[7];
    const float* gamma = (const float*)d_in[8];
    float* out = (float*)d_out;

    cudaFuncSetAttribute(pass1_kernel,
                         cudaFuncAttributeMaxDynamicSharedMemorySize, SMEM1_BYTES);
    cudaFuncSetAttribute(pass2_kernel,
                         cudaFuncAttributeMaxDynamicSharedMemorySize, SMEM2_BYTES);

    dim3 grid(NPARTS, BATCH);
    pass1_kernel<<<grid, 256, SMEM1_BYTES>>>(x, x1, Wk, bk);

    const int R4 = BATCH * CQ * C / 4 + BATCH * C / 4 + BATCH * CQ / 4;
    mid1_kernel<<<(R4 + 255) / 256, 256>>>();
    mid2_kernel<<<64, 256>>>(Wv, bv);

    pass2_kernel<<<grid, 256, SMEM2_BYTES>>>(x1, Wq, bq, gamma, out);
}